// round 14
// baseline (speedup 1.0000x reference)
#include <cuda_runtime.h>
#include <math.h>

// Problem dims
#define Bq      32
#define Dq      512
#define Hq      1024
#define FOURH   4096
#define KTOT    1536            // H + D combined reduction dim
#define KSPLIT  8
#define KCHUNK  (KTOT / KSPLIT) // 192
#define PSPLIT  16              // plastic i-splits per batch
#define PCHUNK  (Hq / PSPLIT)   // 64

#define NPLAST  (Bq * PSPLIT)   // 512 plastic blocks (first in grid)
#define NGEMM   (32 * KSPLIT)   // 256 gemm blocks

// Scratch (static __device__ — no allocation)
__device__ float g_part[KSPLIT][Bq * FOURH];        // GEMM partials (4 MB)
__device__ float g_plastic_part[NPLAST * Hq];       // plastic partials (2 MB)
__device__ float g_tanhg[Bq * Hq];                  // tanh(cell gate) (128 KB)

// ---------------------------------------------------------------------------
// K1 (fused, R13-measured 34.8us at PSPLIT=8): plastic blocks then gemm.
//
// Plastic (R2-proven body, now 512 blocks x 64 rows): 8 float4 loads in
// flight per 4-row group; gemm branch pins regs high, which preserves the
// load batch (R6 lesson).
//
// GEMM (R10-proven transposed-A): C[b][j] = sum_k A[k][b]*W[k][j]
// ---------------------------------------------------------------------------
__global__ __launch_bounds__(256)
void fused_k1(const float* __restrict__ x,  const float* __restrict__ h0,
              const float* __restrict__ Wh, const float* __restrict__ Wx,
              const float* __restrict__ alpha, const float* __restrict__ Hebb0)
{
    if (blockIdx.x < NPLAST) {
        // ---------------- plastic partials ----------------
        __shared__ float h0s[PCHUNK];
        const int b  = blockIdx.x >> 4;
        const int sp = blockIdx.x & 15;
        const int i0 = sp * PCHUNK;
        const int tid = threadIdx.x;

        if (tid < PCHUNK) h0s[tid] = h0[b * Hq + i0 + tid];
        __syncthreads();

        const float4* Ap = (const float4*)(alpha + (size_t)i0 * Hq) + tid;
        const float4* Hp = (const float4*)(Hebb0 + (size_t)b * Hq * Hq
                                                 + (size_t)i0 * Hq) + tid;
        const int rs = Hq / 4;  // row stride in float4

        float4 acc = make_float4(0.f, 0.f, 0.f, 0.f);
        for (int i = 0; i < PCHUNK; i += 4) {
            float4 a0 = Ap[(size_t)(i + 0) * rs];
            float4 a1 = Ap[(size_t)(i + 1) * rs];
            float4 a2 = Ap[(size_t)(i + 2) * rs];
            float4 a3 = Ap[(size_t)(i + 3) * rs];
            float4 v0 = Hp[(size_t)(i + 0) * rs];
            float4 v1 = Hp[(size_t)(i + 1) * rs];
            float4 v2 = Hp[(size_t)(i + 2) * rs];
            float4 v3 = Hp[(size_t)(i + 3) * rs];
            float s0 = h0s[i], s1 = h0s[i+1], s2 = h0s[i+2], s3 = h0s[i+3];
            acc.x += s0*a0.x*v0.x; acc.y += s0*a0.y*v0.y; acc.z += s0*a0.z*v0.z; acc.w += s0*a0.w*v0.w;
            acc.x += s1*a1.x*v1.x; acc.y += s1*a1.y*v1.y; acc.z += s1*a1.z*v1.z; acc.w += s1*a1.w*v1.w;
            acc.x += s2*a2.x*v2.x; acc.y += s2*a2.y*v2.y; acc.z += s2*a2.z*v2.z; acc.w += s2*a2.w*v2.w;
            acc.x += s3*a3.x*v3.x; acc.y += s3*a3.y*v3.y; acc.z += s3*a3.z*v3.z; acc.w += s3*a3.w*v3.w;
        }
        float4* outp = (float4*)(g_plastic_part + (size_t)blockIdx.x * Hq);
        outp[tid] = acc;
    } else {
        // ---------------- gemm partials (transposed-A, R10) ----------------
        __shared__ float Ws[32][128];
        __shared__ float As[32][33];   // [b][k], padded

        const int gid = blockIdx.x - NPLAST;
        const int jt  = gid & 31;       // j tile (128 wide)
        const int ks  = gid >> 5;       // k split (0..7)
        const int tid = threadIdx.x;
        const int tj  = tid & 31;
        const int tb  = tid >> 5;

        float acc[4][4];
#pragma unroll
        for (int i = 0; i < 4; i++)
#pragma unroll
            for (int j = 0; j < 4; j++) acc[i][j] = 0.f;

        const int k0base = ks * KCHUNK;
        const int jbase  = jt * 128;

        const float4* Wh4 = (const float4*)Wh;   // row stride 1024 float4
        const float4* Wx4 = (const float4*)Wx;

        for (int t = 0; t < KCHUNK / 32; t++) {
            const int k0 = k0base + t * 32;
            __syncthreads();
#pragma unroll
            for (int s = 0; s < 4; s++) {
                int lin = s * 256 + tid;
                int kk = lin >> 5, j4 = lin & 31;
                int k = k0 + kk;
                float4 w = (k < Hq) ? Wh4[(size_t)k * 1024 + (jbase >> 2) + j4]
                                    : Wx4[(size_t)(k - Hq) * 1024 + (jbase >> 2) + j4];
                *(float4*)&Ws[kk][j4 * 4] = w;
            }
#pragma unroll
            for (int s = 0; s < 4; s++) {
                int lin = s * 256 + tid;
                int bb = lin >> 5, kk = lin & 31;
                int k = k0 + kk;
                As[bb][kk] = (k < Hq) ? h0[bb * Hq + k] : x[bb * Dq + (k - Hq)];
            }
            __syncthreads();
#pragma unroll
            for (int kk = 0; kk < 32; kk++) {
                float4 w = *(const float4*)&Ws[kk][tj * 4];
                float a0 = As[tb * 4 + 0][kk];
                float a1 = As[tb * 4 + 1][kk];
                float a2 = As[tb * 4 + 2][kk];
                float a3 = As[tb * 4 + 3][kk];
                acc[0][0] += a0*w.x; acc[0][1] += a0*w.y; acc[0][2] += a0*w.z; acc[0][3] += a0*w.w;
                acc[1][0] += a1*w.x; acc[1][1] += a1*w.y; acc[1][2] += a1*w.z; acc[1][3] += a1*w.w;
                acc[2][0] += a2*w.x; acc[2][1] += a2*w.y; acc[2][2] += a2*w.z; acc[2][3] += a2*w.w;
                acc[3][0] += a3*w.x; acc[3][1] += a3*w.y; acc[3][2] += a3*w.z; acc[3][3] += a3*w.w;
            }
        }

        float* outp = g_part[ks];
#pragma unroll
        for (int bb = 0; bb < 4; bb++) {
            int b = tb * 4 + bb;
            int base = b * FOURH + jbase + tj * 4;
            *(float4*)&outp[base] = make_float4(acc[bb][0], acc[bb][1], acc[bb][2], acc[bb][3]);
        }
    }
}

// ---------------------------------------------------------------------------
// K2: pointwise gates -> h1, c1, tanh_g  (8 gemm + 16 plastic partials)
// ---------------------------------------------------------------------------
__global__ __launch_bounds__(256)
void pointwise_kernel(const float* __restrict__ c0, const float* __restrict__ bias,
                      float* __restrict__ out)
{
    const int idx = blockIdx.x * 256 + threadIdx.x;   // 0..32767
    const int b = idx >> 10, h = idx & 1023;

    float g4[4];
#pragma unroll
    for (int c = 0; c < 4; c++) {
        float v = bias[c * Hq + h];
        int base = b * FOURH + c * Hq + h;
#pragma unroll
        for (int s = 0; s < KSPLIT; s++) v += g_part[s][base];
        g4[c] = v;
    }
    float pl = 0.f;
#pragma unroll
    for (int s = 0; s < PSPLIT; s++)
        pl += g_plastic_part[(size_t)(b * PSPLIT + s) * Hq + h];
    g4[3] += pl;

    float fg = 1.f / (1.f + expf(-g4[0]));
    float ig = 1.f / (1.f + expf(-g4[1]));
    float og = 1.f / (1.f + expf(-g4[2]));
    float tg = tanhf(g4[3]);
    float c1 = fg * c0[idx] + ig * tg;
    float h1 = og * tanhf(c1);

    out[idx]           = h1;  // h1 block
    out[Bq * Hq + idx] = c1;  // c1 block
    g_tanhg[idx] = tg;
}

// ---------------------------------------------------------------------------
// K3: Hebb1[b,h,i] = clip(Hebb0[b,h,i] + eta*h0[b,h]*tanh_g[b,i], -1, 1)
// R8-proven 4-row version (measured ~36.5us, 74% DRAM across 4 rounds).
// Reversed order: plastic ends on high-b slices; reversed hebb re-reads
// them from L2 first.
// ---------------------------------------------------------------------------
__global__ __launch_bounds__(256)
void hebb_kernel(const float* __restrict__ Hebb0, const float* __restrict__ h0,
                 const float* __restrict__ eta, float* __restrict__ HebbOut)
{
    const int r0 = (Bq * Hq - 4) - blockIdx.x * 4;   // reversed, 4-row group
    const int b  = r0 >> 10;
    const float e = eta[0];
    const int t = threadIdx.x;

    float4 tv = ((const float4*)(g_tanhg + (size_t)b * Hq))[t];

    const float4* in4 = (const float4*)(Hebb0   + (size_t)r0 * Hq) + t;
    float4*       o4  = (float4*)      (HebbOut + (size_t)r0 * Hq) + t;

    float c0f = e * h0[r0 + 0];
    float c1f = e * h0[r0 + 1];
    float c2f = e * h0[r0 + 2];
    float c3f = e * h0[r0 + 3];

    float4 v0 = __ldcs(in4 + 0 * 256);
    float4 v1 = __ldcs(in4 + 1 * 256);
    float4 v2 = __ldcs(in4 + 2 * 256);
    float4 v3 = __ldcs(in4 + 3 * 256);

    float4 o;
    o.x = fminf(1.f, fmaxf(-1.f, fmaf(c0f, tv.x, v0.x)));
    o.y = fminf(1.f, fmaxf(-1.f, fmaf(c0f, tv.y, v0.y)));
    o.z = fminf(1.f, fmaxf(-1.f, fmaf(c0f, tv.z, v0.z)));
    o.w = fminf(1.f, fmaxf(-1.f, fmaf(c0f, tv.w, v0.w)));
    __stcs(o4 + 0 * 256, o);
    o.x = fminf(1.f, fmaxf(-1.f, fmaf(c1f, tv.x, v1.x)));
    o.y = fminf(1.f, fmaxf(-1.f, fmaf(c1f, tv.y, v1.y)));
    o.z = fminf(1.f, fmaxf(-1.f, fmaf(c1f, tv.z, v1.z)));
    o.w = fminf(1.f, fmaxf(-1.f, fmaf(c1f, tv.w, v1.w)));
    __stcs(o4 + 1 * 256, o);
    o.x = fminf(1.f, fmaxf(-1.f, fmaf(c2f, tv.x, v2.x)));
    o.y = fminf(1.f, fmaxf(-1.f, fmaf(c2f, tv.y, v2.y)));
    o.z = fminf(1.f, fmaxf(-1.f, fmaf(c2f, tv.z, v2.z)));
    o.w = fminf(1.f, fmaxf(-1.f, fmaf(c2f, tv.w, v2.w)));
    __stcs(o4 + 2 * 256, o);
    o.x = fminf(1.f, fmaxf(-1.f, fmaf(c3f, tv.x, v3.x)));
    o.y = fminf(1.f, fmaxf(-1.f, fmaf(c3f, tv.y, v3.y)));
    o.z = fminf(1.f, fmaxf(-1.f, fmaf(c3f, tv.z, v3.z)));
    o.w = fminf(1.f, fmaxf(-1.f, fmaf(c3f, tv.w, v3.w)));
    __stcs(o4 + 3 * 256, o);
}

// ---------------------------------------------------------------------------
// Inputs: x, h0, c0, Hebb0, weight_h, weight_x, bias, alpha, eta
// Output: [h1 (B*H) | c1 (B*H) | Hebb1 (B*H*H)] float32
// ---------------------------------------------------------------------------
extern "C" void kernel_launch(void* const* d_in, const int* in_sizes, int n_in,
                              void* d_out, int out_size)
{
    const float* x     = (const float*)d_in[0];
    const float* h0    = (const float*)d_in[1];
    const float* c0    = (const float*)d_in[2];
    const float* Hebb0 = (const float*)d_in[3];
    const float* Wh    = (const float*)d_in[4];
    const float* Wx    = (const float*)d_in[5];
    const float* bias  = (const float*)d_in[6];
    const float* alpha = (const float*)d_in[7];
    const float* eta   = (const float*)d_in[8];
    float* out = (float*)d_out;

    fused_k1<<<NPLAST + NGEMM, 256>>>(x, h0, Wh, Wx, alpha, Hebb0);
    pointwise_kernel<<<(Bq * Hq) / 256, 256>>>(c0, bias, out);
    hebb_kernel<<<(Bq * Hq) / 4, 256>>>(Hebb0, h0, eta, out + 2 * Bq * Hq);
}

// round 15
// speedup vs baseline: 1.0702x; 1.0702x over previous
#include <cuda_runtime.h>
#include <math.h>

// Problem dims
#define Bq      32
#define Dq      512
#define Hq      1024
#define FOURH   4096
#define KTOT    1536            // H + D combined reduction dim
#define KSPLIT  8
#define KCHUNK  (KTOT / KSPLIT) // 192
#define PSPLIT  16              // plastic i-splits per batch
#define PCHUNK  (Hq / PSPLIT)   // 64

#define NPLAST  (Bq * PSPLIT)   // 512 plastic blocks
#define NGEMM   (32 * KSPLIT)   // 256 gemm blocks
#define NTOT    (NPLAST + NGEMM) // 768; gemm = every 3rd block index

// Scratch (static __device__ — no allocation)
__device__ float g_part[KSPLIT][Bq * FOURH];        // GEMM partials (4 MB)
__device__ float g_plastic_part[NPLAST * Hq];       // plastic partials (2 MB)
__device__ float g_tanhg[Bq * Hq];                  // tanh(cell gate) (128 KB)

// ---------------------------------------------------------------------------
// K1 (fused, interleaved): block i -> gemm if i%3==2 (g=i/3), else plastic
// (p = i - i/3 - (i%3==2?1:0) simplified below). Each wave carries a 2:1
// plastic:gemm mix so DRAM streams and FMA work overlap throughout.
// ---------------------------------------------------------------------------
__global__ __launch_bounds__(256)
void fused_k1(const float* __restrict__ x,  const float* __restrict__ h0,
              const float* __restrict__ Wh, const float* __restrict__ Wx,
              const float* __restrict__ alpha, const float* __restrict__ Hebb0)
{
    const int bi = blockIdx.x;
    if (bi % 3 != 2) {
        // ---------------- plastic partials (R2/R13-proven body) -------------
        const int p = bi - bi / 3;          // 0..511
        __shared__ float h0s[PCHUNK];
        const int b  = p >> 4;
        const int sp = p & 15;
        const int i0 = sp * PCHUNK;
        const int tid = threadIdx.x;

        if (tid < PCHUNK) h0s[tid] = h0[b * Hq + i0 + tid];
        __syncthreads();

        const float4* Ap = (const float4*)(alpha + (size_t)i0 * Hq) + tid;
        const float4* Hp = (const float4*)(Hebb0 + (size_t)b * Hq * Hq
                                                 + (size_t)i0 * Hq) + tid;
        const int rs = Hq / 4;  // row stride in float4

        float4 acc = make_float4(0.f, 0.f, 0.f, 0.f);
        for (int i = 0; i < PCHUNK; i += 4) {
            float4 a0 = Ap[(size_t)(i + 0) * rs];
            float4 a1 = Ap[(size_t)(i + 1) * rs];
            float4 a2 = Ap[(size_t)(i + 2) * rs];
            float4 a3 = Ap[(size_t)(i + 3) * rs];
            float4 v0 = Hp[(size_t)(i + 0) * rs];
            float4 v1 = Hp[(size_t)(i + 1) * rs];
            float4 v2 = Hp[(size_t)(i + 2) * rs];
            float4 v3 = Hp[(size_t)(i + 3) * rs];
            float s0 = h0s[i], s1 = h0s[i+1], s2 = h0s[i+2], s3 = h0s[i+3];
            acc.x += s0*a0.x*v0.x; acc.y += s0*a0.y*v0.y; acc.z += s0*a0.z*v0.z; acc.w += s0*a0.w*v0.w;
            acc.x += s1*a1.x*v1.x; acc.y += s1*a1.y*v1.y; acc.z += s1*a1.z*v1.z; acc.w += s1*a1.w*v1.w;
            acc.x += s2*a2.x*v2.x; acc.y += s2*a2.y*v2.y; acc.z += s2*a2.z*v2.z; acc.w += s2*a2.w*v2.w;
            acc.x += s3*a3.x*v3.x; acc.y += s3*a3.y*v3.y; acc.z += s3*a3.z*v3.z; acc.w += s3*a3.w*v3.w;
        }
        float4* outp = (float4*)(g_plastic_part + (size_t)p * Hq);
        outp[tid] = acc;
    } else {
        // ---------------- gemm partials (transposed-A, R10-proven) ----------
        const int gid = bi / 3;             // 0..255
        __shared__ float Ws[32][128];
        __shared__ float As[32][33];        // [b][k], padded

        const int jt  = gid & 31;           // j tile (128 wide)
        const int ks  = gid >> 5;           // k split (0..7)
        const int tid = threadIdx.x;
        const int tj  = tid & 31;
        const int tb  = tid >> 5;

        float acc[4][4];
#pragma unroll
        for (int i = 0; i < 4; i++)
#pragma unroll
            for (int j = 0; j < 4; j++) acc[i][j] = 0.f;

        const int k0base = ks * KCHUNK;
        const int jbase  = jt * 128;

        const float4* Wh4 = (const float4*)Wh;   // row stride 1024 float4
        const float4* Wx4 = (const float4*)Wx;

        for (int t = 0; t < KCHUNK / 32; t++) {
            const int k0 = k0base + t * 32;
            __syncthreads();
#pragma unroll
            for (int s = 0; s < 4; s++) {
                int lin = s * 256 + tid;
                int kk = lin >> 5, j4 = lin & 31;
                int k = k0 + kk;
                float4 w = (k < Hq) ? Wh4[(size_t)k * 1024 + (jbase >> 2) + j4]
                                    : Wx4[(size_t)(k - Hq) * 1024 + (jbase >> 2) + j4];
                *(float4*)&Ws[kk][j4 * 4] = w;
            }
#pragma unroll
            for (int s = 0; s < 4; s++) {
                int lin = s * 256 + tid;
                int bb = lin >> 5, kk = lin & 31;
                int k = k0 + kk;
                As[bb][kk] = (k < Hq) ? h0[bb * Hq + k] : x[bb * Dq + (k - Hq)];
            }
            __syncthreads();
#pragma unroll
            for (int kk = 0; kk < 32; kk++) {
                float4 w = *(const float4*)&Ws[kk][tj * 4];
                float a0 = As[tb * 4 + 0][kk];
                float a1 = As[tb * 4 + 1][kk];
                float a2 = As[tb * 4 + 2][kk];
                float a3 = As[tb * 4 + 3][kk];
                acc[0][0] += a0*w.x; acc[0][1] += a0*w.y; acc[0][2] += a0*w.z; acc[0][3] += a0*w.w;
                acc[1][0] += a1*w.x; acc[1][1] += a1*w.y; acc[1][2] += a1*w.z; acc[1][3] += a1*w.w;
                acc[2][0] += a2*w.x; acc[2][1] += a2*w.y; acc[2][2] += a2*w.z; acc[2][3] += a2*w.w;
                acc[3][0] += a3*w.x; acc[3][1] += a3*w.y; acc[3][2] += a3*w.z; acc[3][3] += a3*w.w;
            }
        }

        float* outp = g_part[ks];
#pragma unroll
        for (int bb = 0; bb < 4; bb++) {
            int b = tb * 4 + bb;
            int base = b * FOURH + jbase + tj * 4;
            *(float4*)&outp[base] = make_float4(acc[bb][0], acc[bb][1], acc[bb][2], acc[bb][3]);
        }
    }
}

// ---------------------------------------------------------------------------
// K2: pointwise gates -> h1, c1, tanh_g  (8 gemm + 16 plastic partials)
// ---------------------------------------------------------------------------
__global__ __launch_bounds__(256)
void pointwise_kernel(const float* __restrict__ c0, const float* __restrict__ bias,
                      float* __restrict__ out)
{
    const int idx = blockIdx.x * 256 + threadIdx.x;   // 0..32767
    const int b = idx >> 10, h = idx & 1023;

    float g4[4];
#pragma unroll
    for (int c = 0; c < 4; c++) {
        float v = bias[c * Hq + h];
        int base = b * FOURH + c * Hq + h;
#pragma unroll
        for (int s = 0; s < KSPLIT; s++) v += g_part[s][base];
        g4[c] = v;
    }
    float pl = 0.f;
#pragma unroll
    for (int s = 0; s < PSPLIT; s++)
        pl += g_plastic_part[(size_t)(b * PSPLIT + s) * Hq + h];
    g4[3] += pl;

    float fg = 1.f / (1.f + expf(-g4[0]));
    float ig = 1.f / (1.f + expf(-g4[1]));
    float og = 1.f / (1.f + expf(-g4[2]));
    float tg = tanhf(g4[3]);
    float c1 = fg * c0[idx] + ig * tg;
    float h1 = og * tanhf(c1);

    out[idx]           = h1;  // h1 block
    out[Bq * Hq + idx] = c1;  // c1 block
    g_tanhg[idx] = tg;
}

// ---------------------------------------------------------------------------
// K3: Hebb1[b,h,i] = clip(Hebb0[b,h,i] + eta*h0[b,h]*tanh_g[b,i], -1, 1)
// R8-proven 4-row version (~36.5us, 74% DRAM across 4 rounds). Reversed
// order: plastic ends on high-b slices; reversed hebb re-reads them from L2.
// ---------------------------------------------------------------------------
__global__ __launch_bounds__(256)
void hebb_kernel(const float* __restrict__ Hebb0, const float* __restrict__ h0,
                 const float* __restrict__ eta, float* __restrict__ HebbOut)
{
    const int r0 = (Bq * Hq - 4) - blockIdx.x * 4;   // reversed, 4-row group
    const int b  = r0 >> 10;
    const float e = eta[0];
    const int t = threadIdx.x;

    float4 tv = ((const float4*)(g_tanhg + (size_t)b * Hq))[t];

    const float4* in4 = (const float4*)(Hebb0   + (size_t)r0 * Hq) + t;
    float4*       o4  = (float4*)      (HebbOut + (size_t)r0 * Hq) + t;

    float c0f = e * h0[r0 + 0];
    float c1f = e * h0[r0 + 1];
    float c2f = e * h0[r0 + 2];
    float c3f = e * h0[r0 + 3];

    float4 v0 = __ldcs(in4 + 0 * 256);
    float4 v1 = __ldcs(in4 + 1 * 256);
    float4 v2 = __ldcs(in4 + 2 * 256);
    float4 v3 = __ldcs(in4 + 3 * 256);

    float4 o;
    o.x = fminf(1.f, fmaxf(-1.f, fmaf(c0f, tv.x, v0.x)));
    o.y = fminf(1.f, fmaxf(-1.f, fmaf(c0f, tv.y, v0.y)));
    o.z = fminf(1.f, fmaxf(-1.f, fmaf(c0f, tv.z, v0.z)));
    o.w = fminf(1.f, fmaxf(-1.f, fmaf(c0f, tv.w, v0.w)));
    __stcs(o4 + 0 * 256, o);
    o.x = fminf(1.f, fmaxf(-1.f, fmaf(c1f, tv.x, v1.x)));
    o.y = fminf(1.f, fmaxf(-1.f, fmaf(c1f, tv.y, v1.y)));
    o.z = fminf(1.f, fmaxf(-1.f, fmaf(c1f, tv.z, v1.z)));
    o.w = fminf(1.f, fmaxf(-1.f, fmaf(c1f, tv.w, v1.w)));
    __stcs(o4 + 1 * 256, o);
    o.x = fminf(1.f, fmaxf(-1.f, fmaf(c2f, tv.x, v2.x)));
    o.y = fminf(1.f, fmaxf(-1.f, fmaf(c2f, tv.y, v2.y)));
    o.z = fminf(1.f, fmaxf(-1.f, fmaf(c2f, tv.z, v2.z)));
    o.w = fminf(1.f, fmaxf(-1.f, fmaf(c2f, tv.w, v2.w)));
    __stcs(o4 + 2 * 256, o);
    o.x = fminf(1.f, fmaxf(-1.f, fmaf(c3f, tv.x, v3.x)));
    o.y = fminf(1.f, fmaxf(-1.f, fmaf(c3f, tv.y, v3.y)));
    o.z = fminf(1.f, fmaxf(-1.f, fmaf(c3f, tv.z, v3.z)));
    o.w = fminf(1.f, fmaxf(-1.f, fmaf(c3f, tv.w, v3.w)));
    __stcs(o4 + 3 * 256, o);
}

// ---------------------------------------------------------------------------
// Inputs: x, h0, c0, Hebb0, weight_h, weight_x, bias, alpha, eta
// Output: [h1 (B*H) | c1 (B*H) | Hebb1 (B*H*H)] float32
// ---------------------------------------------------------------------------
extern "C" void kernel_launch(void* const* d_in, const int* in_sizes, int n_in,
                              void* d_out, int out_size)
{
    const float* x     = (const float*)d_in[0];
    const float* h0    = (const float*)d_in[1];
    const float* c0    = (const float*)d_in[2];
    const float* Hebb0 = (const float*)d_in[3];
    const float* Wh    = (const float*)d_in[4];
    const float* Wx    = (const float*)d_in[5];
    const float* bias  = (const float*)d_in[6];
    const float* alpha = (const float*)d_in[7];
    const float* eta   = (const float*)d_in[8];
    float* out = (float*)d_out;

    fused_k1<<<NTOT, 256>>>(x, h0, Wh, Wx, alpha, Hebb0);
    pointwise_kernel<<<(Bq * Hq) / 256, 256>>>(c0, bias, out);
    hebb_kernel<<<(Bq * Hq) / 4, 256>>>(Hebb0, h0, eta, out + 2 * Bq * Hq);
}

// round 16
// speedup vs baseline: 1.1114x; 1.0385x over previous
#include <cuda_runtime.h>
#include <math.h>

// Problem dims
#define Bq      32
#define Dq      512
#define Hq      1024
#define FOURH   4096
#define KTOT    1536            // H + D combined reduction dim
#define KSPLIT  8
#define KCHUNK  (KTOT / KSPLIT) // 192
#define PSPLIT  8               // plastic i-splits per batch
#define PCHUNK  (Hq / PSPLIT)   // 128

#define NPLAST  (Bq * PSPLIT)   // 256 plastic blocks (first in grid)
#define NGEMM   (32 * KSPLIT)   // 256 gemm blocks

// Scratch (static __device__ — no allocation)
__device__ float g_part[KSPLIT][Bq * FOURH];        // GEMM partials (4 MB)
__device__ float g_plastic_part[NPLAST * Hq];       // plastic partials (1 MB)
__device__ float g_tanhg[Bq * Hq];                  // tanh(cell gate) (128 KB)

// ---------------------------------------------------------------------------
// K1 (fused, R13-measured 34.8us): blocks [0,256) plastic, [256,512) gemm.
// BYTE-IDENTICAL to the R13 winner.
// ---------------------------------------------------------------------------
__global__ __launch_bounds__(256)
void fused_k1(const float* __restrict__ x,  const float* __restrict__ h0,
              const float* __restrict__ Wh, const float* __restrict__ Wx,
              const float* __restrict__ alpha, const float* __restrict__ Hebb0)
{
    if (blockIdx.x < NPLAST) {
        // ---------------- plastic partials ----------------
        __shared__ float h0s[PCHUNK];
        const int b  = blockIdx.x >> 3;
        const int sp = blockIdx.x & 7;
        const int i0 = sp * PCHUNK;
        const int tid = threadIdx.x;

        if (tid < PCHUNK) h0s[tid] = h0[b * Hq + i0 + tid];
        __syncthreads();

        const float4* Ap = (const float4*)(alpha + (size_t)i0 * Hq) + tid;
        const float4* Hp = (const float4*)(Hebb0 + (size_t)b * Hq * Hq
                                                 + (size_t)i0 * Hq) + tid;
        const int rs = Hq / 4;  // row stride in float4

        float4 acc = make_float4(0.f, 0.f, 0.f, 0.f);
        for (int i = 0; i < PCHUNK; i += 4) {
            float4 a0 = Ap[(size_t)(i + 0) * rs];
            float4 a1 = Ap[(size_t)(i + 1) * rs];
            float4 a2 = Ap[(size_t)(i + 2) * rs];
            float4 a3 = Ap[(size_t)(i + 3) * rs];
            float4 v0 = Hp[(size_t)(i + 0) * rs];
            float4 v1 = Hp[(size_t)(i + 1) * rs];
            float4 v2 = Hp[(size_t)(i + 2) * rs];
            float4 v3 = Hp[(size_t)(i + 3) * rs];
            float s0 = h0s[i], s1 = h0s[i+1], s2 = h0s[i+2], s3 = h0s[i+3];
            acc.x += s0*a0.x*v0.x; acc.y += s0*a0.y*v0.y; acc.z += s0*a0.z*v0.z; acc.w += s0*a0.w*v0.w;
            acc.x += s1*a1.x*v1.x; acc.y += s1*a1.y*v1.y; acc.z += s1*a1.z*v1.z; acc.w += s1*a1.w*v1.w;
            acc.x += s2*a2.x*v2.x; acc.y += s2*a2.y*v2.y; acc.z += s2*a2.z*v2.z; acc.w += s2*a2.w*v2.w;
            acc.x += s3*a3.x*v3.x; acc.y += s3*a3.y*v3.y; acc.z += s3*a3.z*v3.z; acc.w += s3*a3.w*v3.w;
        }
        float4* outp = (float4*)(g_plastic_part + (size_t)blockIdx.x * Hq);
        outp[tid] = acc;
    } else {
        // ---------------- gemm partials (transposed-A, R10) ----------------
        __shared__ float Ws[32][128];
        __shared__ float As[32][33];   // [b][k], padded

        const int gid = blockIdx.x - NPLAST;
        const int jt  = gid & 31;       // j tile (128 wide)
        const int ks  = gid >> 5;       // k split (0..7)
        const int tid = threadIdx.x;
        const int tj  = tid & 31;
        const int tb  = tid >> 5;

        float acc[4][4];
#pragma unroll
        for (int i = 0; i < 4; i++)
#pragma unroll
            for (int j = 0; j < 4; j++) acc[i][j] = 0.f;

        const int k0base = ks * KCHUNK;
        const int jbase  = jt * 128;

        const float4* Wh4 = (const float4*)Wh;   // row stride 1024 float4
        const float4* Wx4 = (const float4*)Wx;

        for (int t = 0; t < KCHUNK / 32; t++) {
            const int k0 = k0base + t * 32;
            __syncthreads();
#pragma unroll
            for (int s = 0; s < 4; s++) {
                int lin = s * 256 + tid;
                int kk = lin >> 5, j4 = lin & 31;
                int k = k0 + kk;
                float4 w = (k < Hq) ? Wh4[(size_t)k * 1024 + (jbase >> 2) + j4]
                                    : Wx4[(size_t)(k - Hq) * 1024 + (jbase >> 2) + j4];
                *(float4*)&Ws[kk][j4 * 4] = w;
            }
#pragma unroll
            for (int s = 0; s < 4; s++) {
                int lin = s * 256 + tid;
                int bb = lin >> 5, kk = lin & 31;
                int k = k0 + kk;
                As[bb][kk] = (k < Hq) ? h0[bb * Hq + k] : x[bb * Dq + (k - Hq)];
            }
            __syncthreads();
#pragma unroll
            for (int kk = 0; kk < 32; kk++) {
                float4 w = *(const float4*)&Ws[kk][tj * 4];
                float a0 = As[tb * 4 + 0][kk];
                float a1 = As[tb * 4 + 1][kk];
                float a2 = As[tb * 4 + 2][kk];
                float a3 = As[tb * 4 + 3][kk];
                acc[0][0] += a0*w.x; acc[0][1] += a0*w.y; acc[0][2] += a0*w.z; acc[0][3] += a0*w.w;
                acc[1][0] += a1*w.x; acc[1][1] += a1*w.y; acc[1][2] += a1*w.z; acc[1][3] += a1*w.w;
                acc[2][0] += a2*w.x; acc[2][1] += a2*w.y; acc[2][2] += a2*w.z; acc[2][3] += a2*w.w;
                acc[3][0] += a3*w.x; acc[3][1] += a3*w.y; acc[3][2] += a3*w.z; acc[3][3] += a3*w.w;
            }
        }

        float* outp = g_part[ks];
#pragma unroll
        for (int bb = 0; bb < 4; bb++) {
            int b = tb * 4 + bb;
            int base = b * FOURH + jbase + tj * 4;
            *(float4*)&outp[base] = make_float4(acc[bb][0], acc[bb][1], acc[bb][2], acc[bb][3]);
        }
    }
}

// ---------------------------------------------------------------------------
// K2: pointwise gates -> h1, c1, tanh_g (128 threads x 256 blocks for
// higher block residency on the 18-load latency-bound body)
// ---------------------------------------------------------------------------
__global__ __launch_bounds__(128)
void pointwise_kernel(const float* __restrict__ c0, const float* __restrict__ bias,
                      float* __restrict__ out)
{
    const int idx = blockIdx.x * 128 + threadIdx.x;   // 0..32767
    const int b = idx >> 10, h = idx & 1023;

    float g4[4];
#pragma unroll
    for (int c = 0; c < 4; c++) {
        float v = bias[c * Hq + h];
        int base = b * FOURH + c * Hq + h;
#pragma unroll
        for (int s = 0; s < KSPLIT; s++) v += g_part[s][base];
        g4[c] = v;
    }
    float pl = 0.f;
#pragma unroll
    for (int s = 0; s < PSPLIT; s++)
        pl += g_plastic_part[(size_t)(b * PSPLIT + s) * Hq + h];
    g4[3] += pl;

    float fg = 1.f / (1.f + expf(-g4[0]));
    float ig = 1.f / (1.f + expf(-g4[1]));
    float og = 1.f / (1.f + expf(-g4[2]));
    float tg = tanhf(g4[3]);
    float c1 = fg * c0[idx] + ig * tg;
    float h1 = og * tanhf(c1);

    out[idx]           = h1;  // h1 block
    out[Bq * Hq + idx] = c1;  // c1 block
    g_tanhg[idx] = tg;
}

// ---------------------------------------------------------------------------
// K3: Hebb1[b,h,i] = clip(Hebb0[b,h,i] + eta*h0[b,h]*tanh_g[b,i], -1, 1)
// 8 rows per block: tanh_g row amortized 8x, 8 independent ldcs in flight.
// Reversed order keeps the L2-tail reuse with the plastic pass.
// ---------------------------------------------------------------------------
__global__ __launch_bounds__(256)
void hebb_kernel(const float* __restrict__ Hebb0, const float* __restrict__ h0,
                 const float* __restrict__ eta, float* __restrict__ HebbOut)
{
    const int r0 = (Bq * Hq - 8) - blockIdx.x * 8;   // reversed, 8-row group
    const int b  = r0 >> 10;
    const float e = eta[0];
    const int t = threadIdx.x;

    float4 tv = ((const float4*)(g_tanhg + (size_t)b * Hq))[t];

    const float4* in4 = (const float4*)(Hebb0   + (size_t)r0 * Hq) + t;
    float4*       o4  = (float4*)      (HebbOut + (size_t)r0 * Hq) + t;

    float cf[8];
#pragma unroll
    for (int r = 0; r < 8; r++) cf[r] = e * h0[r0 + r];

    float4 v[8];
#pragma unroll
    for (int r = 0; r < 8; r++) v[r] = __ldcs(in4 + r * 256);

#pragma unroll
    for (int r = 0; r < 8; r++) {
        float4 o;
        o.x = fminf(1.f, fmaxf(-1.f, fmaf(cf[r], tv.x, v[r].x)));
        o.y = fminf(1.f, fmaxf(-1.f, fmaf(cf[r], tv.y, v[r].y)));
        o.z = fminf(1.f, fmaxf(-1.f, fmaf(cf[r], tv.z, v[r].z)));
        o.w = fminf(1.f, fmaxf(-1.f, fmaf(cf[r], tv.w, v[r].w)));
        __stcs(o4 + r * 256, o);
    }
}

// ---------------------------------------------------------------------------
// Inputs: x, h0, c0, Hebb0, weight_h, weight_x, bias, alpha, eta
// Output: [h1 (B*H) | c1 (B*H) | Hebb1 (B*H*H)] float32
// ---------------------------------------------------------------------------
extern "C" void kernel_launch(void* const* d_in, const int* in_sizes, int n_in,
                              void* d_out, int out_size)
{
    const float* x     = (const float*)d_in[0];
    const float* h0    = (const float*)d_in[1];
    const float* c0    = (const float*)d_in[2];
    const float* Hebb0 = (const float*)d_in[3];
    const float* Wh    = (const float*)d_in[4];
    const float* Wx    = (const float*)d_in[5];
    const float* bias  = (const float*)d_in[6];
    const float* alpha = (const float*)d_in[7];
    const float* eta   = (const float*)d_in[8];
    float* out = (float*)d_out;

    fused_k1<<<NPLAST + NGEMM, 256>>>(x, h0, Wh, Wx, alpha, Hebb0);
    pointwise_kernel<<<(Bq * Hq) / 128, 128>>>(c0, bias, out);
    hebb_kernel<<<(Bq * Hq) / 8, 256>>>(Hebb0, h0, eta, out + 2 * Bq * Hq);
}

// round 17
// speedup vs baseline: 1.1279x; 1.0148x over previous
#include <cuda_runtime.h>
#include <math.h>

// Problem dims
#define Bq      32
#define Dq      512
#define Hq      1024
#define FOURH   4096
#define KTOT    1536            // H + D combined reduction dim
#define KSPLIT  8
#define KCHUNK  (KTOT / KSPLIT) // 192
#define PSPLIT  8               // plastic i-splits per batch
#define PCHUNK  (Hq / PSPLIT)   // 128

#define NPLAST  (Bq * PSPLIT)   // 256 plastic blocks (first in grid)
#define NGEMM   (32 * KSPLIT)   // 256 gemm blocks

// Scratch (static __device__ — no allocation)
__device__ float g_part[KSPLIT][Bq * FOURH];        // GEMM partials (4 MB)
__device__ float g_plastic_part[NPLAST * Hq];       // plastic partials (1 MB)
__device__ float g_tanhg[Bq * Hq];                  // tanh(cell gate) (128 KB)

// ---------------------------------------------------------------------------
// K1 (fused): blocks [0,256) plastic, [256,512) gemm. R13 bodies, but capped
// at 64 regs (4 blocks/SM) so all 512 blocks fit in ONE wave (592 slots).
// ---------------------------------------------------------------------------
__global__ __launch_bounds__(256, 4)
void fused_k1(const float* __restrict__ x,  const float* __restrict__ h0,
              const float* __restrict__ Wh, const float* __restrict__ Wx,
              const float* __restrict__ alpha, const float* __restrict__ Hebb0)
{
    if (blockIdx.x < NPLAST) {
        // ---------------- plastic partials (R2/R13-proven body) -------------
        __shared__ float h0s[PCHUNK];
        const int b  = blockIdx.x >> 3;
        const int sp = blockIdx.x & 7;
        const int i0 = sp * PCHUNK;
        const int tid = threadIdx.x;

        if (tid < PCHUNK) h0s[tid] = h0[b * Hq + i0 + tid];
        __syncthreads();

        const float4* Ap = (const float4*)(alpha + (size_t)i0 * Hq) + tid;
        const float4* Hp = (const float4*)(Hebb0 + (size_t)b * Hq * Hq
                                                 + (size_t)i0 * Hq) + tid;
        const int rs = Hq / 4;  // row stride in float4

        float4 acc = make_float4(0.f, 0.f, 0.f, 0.f);
        for (int i = 0; i < PCHUNK; i += 4) {
            float4 a0 = Ap[(size_t)(i + 0) * rs];
            float4 a1 = Ap[(size_t)(i + 1) * rs];
            float4 a2 = Ap[(size_t)(i + 2) * rs];
            float4 a3 = Ap[(size_t)(i + 3) * rs];
            float4 v0 = Hp[(size_t)(i + 0) * rs];
            float4 v1 = Hp[(size_t)(i + 1) * rs];
            float4 v2 = Hp[(size_t)(i + 2) * rs];
            float4 v3 = Hp[(size_t)(i + 3) * rs];
            float s0 = h0s[i], s1 = h0s[i+1], s2 = h0s[i+2], s3 = h0s[i+3];
            acc.x += s0*a0.x*v0.x; acc.y += s0*a0.y*v0.y; acc.z += s0*a0.z*v0.z; acc.w += s0*a0.w*v0.w;
            acc.x += s1*a1.x*v1.x; acc.y += s1*a1.y*v1.y; acc.z += s1*a1.z*v1.z; acc.w += s1*a1.w*v1.w;
            acc.x += s2*a2.x*v2.x; acc.y += s2*a2.y*v2.y; acc.z += s2*a2.z*v2.z; acc.w += s2*a2.w*v2.w;
            acc.x += s3*a3.x*v3.x; acc.y += s3*a3.y*v3.y; acc.z += s3*a3.z*v3.z; acc.w += s3*a3.w*v3.w;
        }
        float4* outp = (float4*)(g_plastic_part + (size_t)blockIdx.x * Hq);
        outp[tid] = acc;
    } else {
        // ---------------- gemm partials (transposed-A, R10) ----------------
        __shared__ float Ws[32][128];
        __shared__ float As[32][33];   // [b][k], padded

        const int gid = blockIdx.x - NPLAST;
        const int jt  = gid & 31;       // j tile (128 wide)
        const int ks  = gid >> 5;       // k split (0..7)
        const int tid = threadIdx.x;
        const int tj  = tid & 31;
        const int tb  = tid >> 5;

        float acc[4][4];
#pragma unroll
        for (int i = 0; i < 4; i++)
#pragma unroll
            for (int j = 0; j < 4; j++) acc[i][j] = 0.f;

        const int k0base = ks * KCHUNK;
        const int jbase  = jt * 128;

        const float4* Wh4 = (const float4*)Wh;   // row stride 1024 float4
        const float4* Wx4 = (const float4*)Wx;

        for (int t = 0; t < KCHUNK / 32; t++) {
            const int k0 = k0base + t * 32;
            __syncthreads();
#pragma unroll
            for (int s = 0; s < 4; s++) {
                int lin = s * 256 + tid;
                int kk = lin >> 5, j4 = lin & 31;
                int k = k0 + kk;
                float4 w = (k < Hq) ? Wh4[(size_t)k * 1024 + (jbase >> 2) + j4]
                                    : Wx4[(size_t)(k - Hq) * 1024 + (jbase >> 2) + j4];
                *(float4*)&Ws[kk][j4 * 4] = w;
            }
#pragma unroll
            for (int s = 0; s < 4; s++) {
                int lin = s * 256 + tid;
                int bb = lin >> 5, kk = lin & 31;
                int k = k0 + kk;
                As[bb][kk] = (k < Hq) ? h0[bb * Hq + k] : x[bb * Dq + (k - Hq)];
            }
            __syncthreads();
#pragma unroll
            for (int kk = 0; kk < 32; kk++) {
                float4 w = *(const float4*)&Ws[kk][tj * 4];
                float a0 = As[tb * 4 + 0][kk];
                float a1 = As[tb * 4 + 1][kk];
                float a2 = As[tb * 4 + 2][kk];
                float a3 = As[tb * 4 + 3][kk];
                acc[0][0] += a0*w.x; acc[0][1] += a0*w.y; acc[0][2] += a0*w.z; acc[0][3] += a0*w.w;
                acc[1][0] += a1*w.x; acc[1][1] += a1*w.y; acc[1][2] += a1*w.z; acc[1][3] += a1*w.w;
                acc[2][0] += a2*w.x; acc[2][1] += a2*w.y; acc[2][2] += a2*w.z; acc[2][3] += a2*w.w;
                acc[3][0] += a3*w.x; acc[3][1] += a3*w.y; acc[3][2] += a3*w.z; acc[3][3] += a3*w.w;
            }
        }

        float* outp = g_part[ks];
#pragma unroll
        for (int bb = 0; bb < 4; bb++) {
            int b = tb * 4 + bb;
            int base = b * FOURH + jbase + tj * 4;
            *(float4*)&outp[base] = make_float4(acc[bb][0], acc[bb][1], acc[bb][2], acc[bb][3]);
        }
    }
}

// ---------------------------------------------------------------------------
// K2: pointwise gates -> h1, c1, tanh_g (128 threads x 256 blocks)
// ---------------------------------------------------------------------------
__global__ __launch_bounds__(128)
void pointwise_kernel(const float* __restrict__ c0, const float* __restrict__ bias,
                      float* __restrict__ out)
{
    const int idx = blockIdx.x * 128 + threadIdx.x;   // 0..32767
    const int b = idx >> 10, h = idx & 1023;

    float g4[4];
#pragma unroll
    for (int c = 0; c < 4; c++) {
        float v = bias[c * Hq + h];
        int base = b * FOURH + c * Hq + h;
#pragma unroll
        for (int s = 0; s < KSPLIT; s++) v += g_part[s][base];
        g4[c] = v;
    }
    float pl = 0.f;
#pragma unroll
    for (int s = 0; s < PSPLIT; s++)
        pl += g_plastic_part[(size_t)(b * PSPLIT + s) * Hq + h];
    g4[3] += pl;

    float fg = 1.f / (1.f + expf(-g4[0]));
    float ig = 1.f / (1.f + expf(-g4[1]));
    float og = 1.f / (1.f + expf(-g4[2]));
    float tg = tanhf(g4[3]);
    float c1 = fg * c0[idx] + ig * tg;
    float h1 = og * tanhf(c1);

    out[idx]           = h1;  // h1 block
    out[Bq * Hq + idx] = c1;  // c1 block
    g_tanhg[idx] = tg;
}

// ---------------------------------------------------------------------------
// K3: Hebb1[b,h,i] = clip(Hebb0[b,h,i] + eta*h0[b,h]*tanh_g[b,i], -1, 1)
// R8-proven 4-row version (~36.5us across 5 measurements). Reversed order:
// plastic ends on high-b slices; reversed hebb re-reads them from L2.
// ---------------------------------------------------------------------------
__global__ __launch_bounds__(256)
void hebb_kernel(const float* __restrict__ Hebb0, const float* __restrict__ h0,
                 const float* __restrict__ eta, float* __restrict__ HebbOut)
{
    const int r0 = (Bq * Hq - 4) - blockIdx.x * 4;   // reversed, 4-row group
    const int b  = r0 >> 10;
    const float e = eta[0];
    const int t = threadIdx.x;

    float4 tv = ((const float4*)(g_tanhg + (size_t)b * Hq))[t];

    const float4* in4 = (const float4*)(Hebb0   + (size_t)r0 * Hq) + t;
    float4*       o4  = (float4*)      (HebbOut + (size_t)r0 * Hq) + t;

    float c0f = e * h0[r0 + 0];
    float c1f = e * h0[r0 + 1];
    float c2f = e * h0[r0 + 2];
    float c3f = e * h0[r0 + 3];

    float4 v0 = __ldcs(in4 + 0 * 256);
    float4 v1 = __ldcs(in4 + 1 * 256);
    float4 v2 = __ldcs(in4 + 2 * 256);
    float4 v3 = __ldcs(in4 + 3 * 256);

    float4 o;
    o.x = fminf(1.f, fmaxf(-1.f, fmaf(c0f, tv.x, v0.x)));
    o.y = fminf(1.f, fmaxf(-1.f, fmaf(c0f, tv.y, v0.y)));
    o.z = fminf(1.f, fmaxf(-1.f, fmaf(c0f, tv.z, v0.z)));
    o.w = fminf(1.f, fmaxf(-1.f, fmaf(c0f, tv.w, v0.w)));
    __stcs(o4 + 0 * 256, o);
    o.x = fminf(1.f, fmaxf(-1.f, fmaf(c1f, tv.x, v1.x)));
    o.y = fminf(1.f, fmaxf(-1.f, fmaf(c1f, tv.y, v1.y)));
    o.z = fminf(1.f, fmaxf(-1.f, fmaf(c1f, tv.z, v1.z)));
    o.w = fminf(1.f, fmaxf(-1.f, fmaf(c1f, tv.w, v1.w)));
    __stcs(o4 + 1 * 256, o);
    o.x = fminf(1.f, fmaxf(-1.f, fmaf(c2f, tv.x, v2.x)));
    o.y = fminf(1.f, fmaxf(-1.f, fmaf(c2f, tv.y, v2.y)));
    o.z = fminf(1.f, fmaxf(-1.f, fmaf(c2f, tv.z, v2.z)));
    o.w = fminf(1.f, fmaxf(-1.f, fmaf(c2f, tv.w, v2.w)));
    __stcs(o4 + 2 * 256, o);
    o.x = fminf(1.f, fmaxf(-1.f, fmaf(c3f, tv.x, v3.x)));
    o.y = fminf(1.f, fmaxf(-1.f, fmaf(c3f, tv.y, v3.y)));
    o.z = fminf(1.f, fmaxf(-1.f, fmaf(c3f, tv.z, v3.z)));
    o.w = fminf(1.f, fmaxf(-1.f, fmaf(c3f, tv.w, v3.w)));
    __stcs(o4 + 3 * 256, o);
}

// ---------------------------------------------------------------------------
// Inputs: x, h0, c0, Hebb0, weight_h, weight_x, bias, alpha, eta
// Output: [h1 (B*H) | c1 (B*H) | Hebb1 (B*H*H)] float32
// ---------------------------------------------------------------------------
extern "C" void kernel_launch(void* const* d_in, const int* in_sizes, int n_in,
                              void* d_out, int out_size)
{
    const float* x     = (const float*)d_in[0];
    const float* h0    = (const float*)d_in[1];
    const float* c0    = (const float*)d_in[2];
    const float* Hebb0 = (const float*)d_in[3];
    const float* Wh    = (const float*)d_in[4];
    const float* Wx    = (const float*)d_in[5];
    const float* bias  = (const float*)d_in[6];
    const float* alpha = (const float*)d_in[7];
    const float* eta   = (const float*)d_in[8];
    float* out = (float*)d_out;

    fused_k1<<<NPLAST + NGEMM, 256>>>(x, h0, Wh, Wx, alpha, Hebb0);
    pointwise_kernel<<<(Bq * Hq) / 128, 128>>>(c0, bias, out);
    hebb_kernel<<<(Bq * Hq) / 4, 256>>>(Hebb0, h0, eta, out + 2 * Bq * Hq);
}